// round 17
// baseline (speedup 1.0000x reference)
#include <cuda_runtime.h>
#include <math.h>

typedef unsigned long long u64;

#define NV    25
#define NE    1600
#define NTHR  256
#define RSF   66              // floats per state row (33 u64)

// shared float offsets
#define O_WT1 0               // Wt[c*64+o] = W[o*64+c]      (4096)
#define O_WT2 4096
#define O_WTP 8192
#define O_AT  12288           // scalar A^T: [u*32+v], pad   (800)
#define O_B1  13088
#define O_B2  13152
#define O_BP  13216
#define O_PE  13280           // 5 rows x 64                 (320)
#define O_BUF 13600           // b0, b1 (4224 each)
#define SMF   (O_BUF + 2 * 64 * RSF)   // 22048 floats
#define SMB   (SMF * 4)                // 88192 bytes -> 2 blocks/SM

extern __shared__ float sm[];

__device__ __forceinline__ u64 pack2(float x) {
    u64 r; asm("mov.b64 %0,{%1,%1};" : "=l"(r) : "f"(x)); return r;
}
__device__ __forceinline__ void fma2(u64& a, u64 x, u64 w) {
    asm("fma.rn.f32x2 %0,%1,%2,%0;" : "+l"(a) : "l"(x), "l"(w));
}
__device__ __forceinline__ float2 unp(u64 a) {
    float2 f; asm("mov.b64 {%0,%1},%2;" : "=f"(f.x), "=f"(f.y) : "l"(a)); return f;
}

// W mainloop: acc[i][k] = sum_c W[o0+i][c] * x[c][jq+16k]   (4o x 2j)
__device__ __forceinline__ void mmW(int wofs, int src, int jq, int o0, u64 acc[4][2])
{
#pragma unroll
    for (int i = 0; i < 4; i++) { acc[i][0] = 0ULL; acc[i][1] = 0ULL; }
#pragma unroll 8
    for (int c = 0; c < 64; c++) {
        const float* xr = sm + src + c * RSF + jq * 2;
        const u64 x0 = *(const u64*)(xr);
        const u64 x1 = *(const u64*)(xr + 32);
        const float4 wa = *(const float4*)(sm + wofs + c * 64 + o0);
        const float wv[4] = {wa.x, wa.y, wa.z, wa.w};
#pragma unroll
        for (int i = 0; i < 4; i++) {
            const u64 wp = pack2(wv[i]);
            fma2(acc[i][0], x0, wp);
            fma2(acc[i][1], x1, wp);
        }
    }
}

// A matmul: dst[c][v] = sum_u At[u][v] * src[c][u]   (2c x 4v)
__device__ __forceinline__ void amat(int src, int dst, int cq, int vb)
{
    u64 acc[2][4];
#pragma unroll
    for (int ci = 0; ci < 2; ci++)
#pragma unroll
        for (int m = 0; m < 4; m++) acc[ci][m] = 0ULL;
#pragma unroll 5
    for (int u = 0; u < NV; u++) {
        const u64 x0 = *(const u64*)(sm + src + cq * RSF + u * 2);
        const u64 x1 = *(const u64*)(sm + src + (cq + 32) * RSF + u * 2);
        const float4 aa = *(const float4*)(sm + O_AT + u * 32 + vb);
        const float av[4] = {aa.x, aa.y, aa.z, aa.w};
#pragma unroll
        for (int m = 0; m < 4; m++) {
            const u64 ap = pack2(av[m]);
            fma2(acc[0][m], x0, ap);
            fma2(acc[1][m], x1, ap);
        }
    }
#pragma unroll
    for (int ci = 0; ci < 2; ci++) {
        float* dr = sm + dst + (cq + 32 * ci) * RSF + vb * 2;
#pragma unroll
        for (int m = 0; m < 4; m++)
            *(u64*)(dr + m * 2) = acc[ci][m];
    }
}

// W stage with bias + leaky relu: src -> dst
__device__ __forceinline__ void wact(int wofs, int bofs, int src, int dst,
                                     int jq, int o0)
{
    u64 acc[4][2];
    mmW(wofs, src, jq, o0, acc);
#pragma unroll
    for (int i = 0; i < 4; i++) {
        const float b = sm[bofs + o0 + i];
        float* dr = sm + dst + (o0 + i) * RSF + jq * 2;
#pragma unroll
        for (int k = 0; k < 2; k++) {
            float2 r = unp(acc[i][k]);
            r.x += b; r.y += b;
            r.x = fmaxf(r.x, 0.01f * r.x);
            r.y = fmaxf(r.y, 0.01f * r.y);
            *(float2*)(dr + 32 * k) = r;
        }
    }
}

// (A, W1+relu, A, W2+relu): arg X -> X, scratch Z
__device__ __forceinline__ void core(int X, int Z, int cq, int vb,
                                     int jq, int o0)
{
    amat(X, Z, cq, vb);              __syncthreads();
    wact(O_WT1, O_B1, Z, X, jq, o0); __syncthreads();
    amat(X, Z, cq, vb);              __syncthreads();
    wact(O_WT2, O_B2, Z, X, jq, o0); __syncthreads();
}

__global__ void __launch_bounds__(NTHR, 2)
sode_kernel(const float* __restrict__ gfp, const float* __restrict__ gts,
            const float* __restrict__ gA,
            const float* __restrict__ gW1, const float* __restrict__ gb1,
            const float* __restrict__ gW2, const float* __restrict__ gb2,
            const float* __restrict__ gWp, const float* __restrict__ gbp,
            const float* __restrict__ gpe,
            float* __restrict__ out, int nb)
{
    const int tid = threadIdx.x;
    const int n0  = blockIdx.x << 1;      // 2 samples per block
    const int tt0 = n0 & 63;
    const int jq  = tid & 15, o0 = (tid >> 4) << 2;
    const int cq  = tid & 31, vb = (tid >> 5) << 2;

    const int b0 = O_BUF;
    const int b1 = O_BUF + 64 * RSF;

    // ---- shared init ----
    for (int i = tid; i < 4096; i += NTHR) {
        const int c = i >> 6, o = i & 63;
        sm[O_WT1 + i] = gW1[o * 64 + c];
        sm[O_WT2 + i] = gW2[o * 64 + c];
        sm[O_WTP + i] = gWp[o * 64 + c];
    }
    for (int i = tid; i < 800; i += NTHR) {
        const int u = i >> 5, v = i & 31;
        sm[O_AT + i] = (v < NV) ? gA[v * NV + u] : 0.f;
    }
    if (tid < 64) {
        sm[O_B1 + tid] = gb1[tid];
        sm[O_B2 + tid] = gb2[tid];
        sm[O_BP + tid] = gbp[tid];
    }
    for (int i = tid; i < 320; i += NTHR) sm[O_PE + i] = gpe[tt0 * 64 + i];

    // ---- Y state in registers; load first_point, emit out[0] ----
    float2 Yr[4][2];
#pragma unroll
    for (int i = 0; i < 4; i++) {
        const int o = o0 + i;
#pragma unroll
        for (int k = 0; k < 2; k++) {
            const int v = jq + 16 * k;
            float2 Yv = make_float2(0.f, 0.f);
            if (v < NV) {
                Yv.x = gfp[(size_t)n0 * NE + o * NV + v];
                Yv.y = gfp[(size_t)(n0 + 1) * NE + o * NV + v];
                out[(size_t)n0 * NE + o * NV + v]       = Yv.x;
                out[(size_t)(n0 + 1) * NE + o * NV + v] = Yv.y;
            }
            Yr[i][k] = Yv;
        }
    }

    // barrier BEFORE prep1: PE/A/weights written by other threads
    __syncthreads();

    float2 k1[4][2], k2[4][2];

    // prep for step 0 eval 1: b0 = Yr + pe(row 0,1)
#pragma unroll
    for (int i = 0; i < 4; i++) {
        const int o = o0 + i;
        const float px = sm[O_PE + o];
        const float py = sm[O_PE + 64 + o];
        float* tr = sm + b0 + o * RSF + jq * 2;
#pragma unroll
        for (int k = 0; k < 2; k++) {
            float2 tb;
            tb.x = Yr[i][k].x + px;
            tb.y = Yr[i][k].y + py;
            *(float2*)(tr + 32 * k) = tb;
        }
    }
    __syncthreads();

#pragma unroll 1
    for (int st = 0; st < 3; st++) {
        const float t0 = gts[st];
        const float dt = gts[st + 1] - t0;
        const int r2 = (int)floorf(t0 + dt * (1.f / 3.f));
        const int r3 = (int)floorf(t0 + dt * (2.f / 3.f));
        const int r4 = (int)floorf(t0 + dt);
        const int rn = (int)floorf(gts[st + 1]);

        // ---- eval 1 (arg b0): k1; b1 <- Yr + dt/3*k1 + pe(r2) ----
        core(b0, b1, cq, vb, jq, o0);
        {
            u64 acc[4][2];
            mmW(O_WTP, b0, jq, o0, acc);
            const float f = dt * (1.f / 3.f);
#pragma unroll
            for (int i = 0; i < 4; i++) {
                const int o = o0 + i;
                const float b = sm[O_BP + o];
                const float px = sm[O_PE + r2 * 64 + o];
                const float py = sm[O_PE + (r2 + 1) * 64 + o];
                float* tr = sm + b1 + o * RSF + jq * 2;
#pragma unroll
                for (int k = 0; k < 2; k++) {
                    float2 v = unp(acc[i][k]);
                    v.x += b; v.y += b;
                    k1[i][k] = v;
                    float2 tb;
                    tb.x = Yr[i][k].x + f * v.x + px;
                    tb.y = Yr[i][k].y + f * v.y + py;
                    *(float2*)(tr + 32 * k) = tb;
                }
            }
            __syncthreads();
        }

        // ---- eval 2 (arg b1): k2; b0 <- Yr + dt*k2 - dt/3*k1 + pe(r3) ----
        core(b1, b0, cq, vb, jq, o0);
        {
            u64 acc[4][2];
            mmW(O_WTP, b1, jq, o0, acc);
            const float f3 = dt * (1.f / 3.f);
#pragma unroll
            for (int i = 0; i < 4; i++) {
                const int o = o0 + i;
                const float b = sm[O_BP + o];
                const float px = sm[O_PE + r3 * 64 + o];
                const float py = sm[O_PE + (r3 + 1) * 64 + o];
                float* tr = sm + b0 + o * RSF + jq * 2;
#pragma unroll
                for (int k = 0; k < 2; k++) {
                    float2 v = unp(acc[i][k]);
                    v.x += b; v.y += b;
                    k2[i][k] = v;
                    float2 tb;
                    tb.x = Yr[i][k].x + dt * v.x - f3 * k1[i][k].x + px;
                    tb.y = Yr[i][k].y + dt * v.y - f3 * k1[i][k].y + py;
                    *(float2*)(tr + 32 * k) = tb;
                }
            }
            __syncthreads();
        }

        // ---- eval 3 (arg b0): k3; b1 <- Yr + dt*(k1-k2+k3) + pe(r4);
        //      k2 <- k1 + 3*(k2+k3) ----
        core(b0, b1, cq, vb, jq, o0);
        {
            u64 acc[4][2];
            mmW(O_WTP, b0, jq, o0, acc);
#pragma unroll
            for (int i = 0; i < 4; i++) {
                const int o = o0 + i;
                const float b = sm[O_BP + o];
                const float px = sm[O_PE + r4 * 64 + o];
                const float py = sm[O_PE + (r4 + 1) * 64 + o];
                float* tr = sm + b1 + o * RSF + jq * 2;
#pragma unroll
                for (int k = 0; k < 2; k++) {
                    float2 k3 = unp(acc[i][k]);
                    k3.x += b; k3.y += b;
                    const float2 K1 = k1[i][k], K2 = k2[i][k];
                    float2 tb, kn;
                    tb.x = Yr[i][k].x + dt * (K1.x - K2.x + k3.x) + px;
                    tb.y = Yr[i][k].y + dt * (K1.y - K2.y + k3.y) + py;
                    kn.x = K1.x + 3.f * (K2.x + k3.x);
                    kn.y = K1.y + 3.f * (K2.y + k3.y);
                    k2[i][k] = kn;
                    *(float2*)(tr + 32 * k) = tb;
                }
            }
            __syncthreads();
        }

        // ---- eval 4 (arg b1): k4; Yr += dt/8*(k2 + k4); emit out[st+1];
        //      fused prep: b0 <- Yrnew + pe(rn) ----
        core(b1, b0, cq, vb, jq, o0);
        {
            u64 acc[4][2];
            mmW(O_WTP, b1, jq, o0, acc);
            float* ob = out + (size_t)(st + 1) * nb * NE + (size_t)n0 * NE;
            const float f = dt * 0.125f;
#pragma unroll
            for (int i = 0; i < 4; i++) {
                const int o = o0 + i;
                const float b = sm[O_BP + o];
                const float px = sm[O_PE + rn * 64 + o];
                const float py = sm[O_PE + (rn + 1) * 64 + o];
                float* tr = sm + b0 + o * RSF + jq * 2;
#pragma unroll
                for (int k = 0; k < 2; k++) {
                    const int v = jq + 16 * k;
                    float2 k4 = unp(acc[i][k]);
                    k4.x += b; k4.y += b;
                    const float2 K2 = k2[i][k];
                    float2 Yv = Yr[i][k];
                    Yv.x += f * (K2.x + k4.x);
                    Yv.y += f * (K2.y + k4.y);
                    Yr[i][k] = Yv;
                    if (v < NV) {
                        ob[o * NV + v]      = Yv.x;
                        ob[NE + o * NV + v] = Yv.y;
                    }
                    float2 tb;
                    tb.x = Yv.x + px;
                    tb.y = Yv.y + py;
                    *(float2*)(tr + 32 * k) = tb;
                }
            }
            __syncthreads();
        }
    }
}

extern "C" void kernel_launch(void* const* d_in, const int* in_sizes, int n_in,
                              void* d_out, int out_size)
{
    const float* fp = (const float*)d_in[0];
    const float* ts = (const float*)d_in[1];
    const float* A  = (const float*)d_in[2];
    const float* W1 = (const float*)d_in[3];
    const float* b1 = (const float*)d_in[4];
    const float* W2 = (const float*)d_in[5];
    const float* b2 = (const float*)d_in[6];
    const float* Wp = (const float*)d_in[7];
    const float* bp = (const float*)d_in[8];
    const float* pe = (const float*)d_in[9];
    float* out = (float*)d_out;

    const int nb = in_sizes[0] / NE;

    cudaFuncSetAttribute(sode_kernel,
                         cudaFuncAttributeMaxDynamicSharedMemorySize, SMB);
    sode_kernel<<<nb / 2, NTHR, SMB>>>(fp, ts, A, W1, b1, W2, b2, Wp, bp, pe,
                                       out, nb);
}